// round 5
// baseline (speedup 1.0000x reference)
#include <cuda_runtime.h>
#include <math.h>

#define BB 65536
#define KK 256
#define DD 128

typedef unsigned long long u64;

// ---- scratch (static device globals; no allocation) ----
__device__ float g_K[(size_t)BB * KK];   // K' = exp(-C/eps) + 1e-8  (64MB) — keep L2-resident
__device__ float g_ynT[DD * KK];         // normalized prototypes, k-major [k][j]
__device__ float g_xinv[BB];             // 1 / ||x_i||
__device__ float g_a[BB];                // exp(u)
__device__ float g_T[3][KK * 32];        // column sums, padded 128B apart
__device__ double g_sum;

// 256-bit L2-pinned load: 8 consecutive floats, biased to stay in L2
__device__ __forceinline__ void ld256_el(const float* p, float* v) {
    u64 a, b, c, d;
    asm volatile("ld.global.L2::evict_last.v4.b64 {%0,%1,%2,%3}, [%4];"
                 : "=l"(a), "=l"(b), "=l"(c), "=l"(d) : "l"(p));
    v[0] = __uint_as_float((unsigned)(a & 0xffffffffull));
    v[1] = __uint_as_float((unsigned)(a >> 32));
    v[2] = __uint_as_float((unsigned)(b & 0xffffffffull));
    v[3] = __uint_as_float((unsigned)(b >> 32));
    v[4] = __uint_as_float((unsigned)(c & 0xffffffffull));
    v[5] = __uint_as_float((unsigned)(c >> 32));
    v[6] = __uint_as_float((unsigned)(d & 0xffffffffull));
    v[7] = __uint_as_float((unsigned)(d >> 32));
}

// ---------------------------------------------------------------------------
__global__ void k_init(const float* __restrict__ proto) {
    int j = threadIdx.x;  // 0..255
    float ss = 0.f;
#pragma unroll 8
    for (int k = 0; k < DD; k++) { float v = proto[j * DD + k]; ss += v * v; }
    float inv = __fdividef(1.f, fmaxf(sqrtf(ss), 1e-12f));
    for (int k = 0; k < DD; k++) g_ynT[k * KK + j] = proto[j * DD + k] * inv;
    const float nuP = 1.f / (float)KK + 1e-8f;
    g_T[0][j * 32] = nuP;   // makes w == 1 on iteration 1 (v0 = 0)
    g_T[1][j * 32] = 0.f;   // accumulation target of iteration 1
    if (j == 0) g_sum = 0.0;
}

// ---------------------------------------------------------------------------
__global__ void k_xnorm(const float* __restrict__ x) {
    int warp = threadIdx.x >> 5, lane = threadIdx.x & 31;
    int row = blockIdx.x * 8 + warp;
    float4 v = ((const float4*)(x + (size_t)row * DD))[lane];
    float ss = v.x * v.x + v.y * v.y + v.z * v.z + v.w * v.w;
#pragma unroll
    for (int o = 16; o; o >>= 1) ss += __shfl_xor_sync(0xffffffffu, ss, o);
    if (lane == 0) g_xinv[row] = __fdividef(1.f, fmaxf(sqrtf(ss), 1e-12f));
}

// ---------------------------------------------------------------------------
// cost GEMM: K' = exp(-10*(1 - xn.yn)) + 1e-8
// block = 256 threads, 64 rows x 256 cols per block, 8x8 register tile/thread
// ---------------------------------------------------------------------------
__global__ void k_gemm(const float* __restrict__ x) {
    __shared__ float ys[32 * 256];  // k-chunk of prototypes [kk][col]  (32KB)
    __shared__ float xs[64 * 32];   // x tile [row][kk]                 (8KB)
    __shared__ float xrn[64];

    int t = threadIdx.x;
    int rowBase = blockIdx.x * 64;
    if (t < 64) xrn[t] = g_xinv[rowBase + t];

    int tx = t & 31, ty = t >> 5;
    float acc[8][8];
#pragma unroll
    for (int i = 0; i < 8; i++)
#pragma unroll
        for (int j = 0; j < 8; j++) acc[i][j] = 0.f;

    for (int kc = 0; kc < 4; kc++) {
        __syncthreads();
        {
            const float4* src = (const float4*)(g_ynT + kc * 32 * 256);
            float4* dst = (float4*)ys;
#pragma unroll
            for (int i = 0; i < 8; i++) dst[t + i * 256] = src[t + i * 256];
        }
        {
#pragma unroll
            for (int i = 0; i < 2; i++) {
                int idx = t + i * 256;
                int r = idx >> 3;
                int c4 = idx & 7;
                float4 v = *(const float4*)(x + (size_t)(rowBase + r) * DD + kc * 32 + c4 * 4);
                *(float4*)&xs[r * 32 + c4 * 4] = v;
            }
        }
        __syncthreads();
#pragma unroll 4
        for (int k = 0; k < 32; k++) {
            float4 b0 = *(const float4*)&ys[k * 256 + tx * 8];
            float4 b1 = *(const float4*)&ys[k * 256 + tx * 8 + 4];
#pragma unroll
            for (int i = 0; i < 8; i++) {
                float a = xs[(ty * 8 + i) * 32 + k];
                acc[i][0] += a * b0.x; acc[i][1] += a * b0.y;
                acc[i][2] += a * b0.z; acc[i][3] += a * b0.w;
                acc[i][4] += a * b1.x; acc[i][5] += a * b1.y;
                acc[i][6] += a * b1.z; acc[i][7] += a * b1.w;
            }
        }
    }

#pragma unroll
    for (int i = 0; i < 8; i++) {
        int row = rowBase + ty * 8 + i;
        float inv = xrn[ty * 8 + i];
        float kv[8];
#pragma unroll
        for (int j = 0; j < 8; j++) {
            float c = 1.f - acc[i][j] * inv;
            kv[j] = __expf(-10.f * c) + 1e-8f;
        }
        size_t base = (size_t)row * KK + tx * 8;
        *(float4*)&g_K[base]     = make_float4(kv[0], kv[1], kv[2], kv[3]);
        *(float4*)&g_K[base + 4] = make_float4(kv[4], kv[5], kv[6], kv[7]);
    }
}

// ---------------------------------------------------------------------------
// Sinkhorn iteration helpers: 2-row batch load / compute
// ---------------------------------------------------------------------------
__device__ __forceinline__ void iter_load(int b, int colOff, float* A) {
    const float* p = g_K + (size_t)b * 2 * KK + colOff;
    ld256_el(p, A);
    ld256_el(p + KK, A + 8);
}

__device__ __forceinline__ void iter_compute(int b, const float* A, const float* w,
                                             float* tj, float muP, int lane) {
    float s0 = 0.f, s1 = 0.f;
#pragma unroll
    for (int m = 0; m < 8; m++) { s0 += A[m] * w[m]; s1 += A[8 + m] * w[m]; }
#pragma unroll
    for (int o = 16; o; o >>= 1) {
        s0 += __shfl_xor_sync(0xffffffffu, s0, o);
        s1 += __shfl_xor_sync(0xffffffffu, s1, o);
    }
    float a0 = muP * __fdividef(1.f, s0);
    float a1 = muP * __fdividef(1.f, s1);
    if (lane == 0) *(float2*)&g_a[b * 2] = make_float2(a0, a1);
#pragma unroll
    for (int m = 0; m < 8; m++) tj[m] += A[m] * a0 + A[8 + m] * a1;
}

// ---------------------------------------------------------------------------
// fused Sinkhorn iteration: w = nu'/T_prev ; a_i = mu'/(K' w)_i ; T_cur += K'^T a
// persistent grid 444; lane owns cols [8l..8l+7]; software-pipelined
// double-buffered 2-row batches (loads overlap compute).
// ---------------------------------------------------------------------------
__global__ void __launch_bounds__(256, 3) k_iter(int prev, int cur, int clr) {
    const float nuP = 1.f / (float)KK + 1e-8f;
    const float muP = 1.f / (float)BB + 1e-8f;
    __shared__ float Ts2[8 * 256];

    int t = threadIdx.x, lane = t & 31, warp = t >> 5;
    if (blockIdx.x == 0) g_T[clr][t * 32] = 0.f;  // clear buffer for NEXT kernel

    float w[8];
#pragma unroll
    for (int m = 0; m < 8; m++)
        w[m] = nuP * __fdividef(1.f, g_T[prev][(lane * 8 + m) * 32]);

    float tj[8] = {0, 0, 0, 0, 0, 0, 0, 0};
    const int nW = 444 * 8;          // 3552 warps
    const int nB = BB / 2;           // 32768 batches of 2 rows
    int gw = blockIdx.x * 8 + warp;
    int colOff = lane * 8;

    float A[16], Bf[16];
    iter_load(gw, colOff, A);        // gw < 3552 < nB always
    for (int b = gw; b < nB; b += 2 * nW) {
        int b1 = b + nW, b2 = b + 2 * nW;
        if (b1 < nB) iter_load(b1, colOff, Bf);
        iter_compute(b, A, w, tj, muP, lane);
        if (b2 < nB) iter_load(b2, colOff, A);
        if (b1 < nB) iter_compute(b1, Bf, w, tj, muP, lane);
    }

#pragma unroll
    for (int m = 0; m < 8; m++)
        Ts2[warp * 256 + lane * 8 + m] = tj[m];
    __syncthreads();
    {
        float s = 0.f;
#pragma unroll
        for (int ww = 0; ww < 8; ww++) s += Ts2[ww * 256 + t];
        atomicAdd(&g_T[cur][t * 32], s);
    }
}

// ---------------------------------------------------------------------------
// final: sum_ij a_i * K'_ij * w_j * C_ij * softmax(|coord_i|)_j
// C reconstructed: C = -0.1 * log(K' - 1e-8). Persistent grid 444.
// ---------------------------------------------------------------------------
__global__ void __launch_bounds__(256, 3) k_final(const float* __restrict__ coord, int cur) {
    const float nuP = 1.f / (float)KK + 1e-8f;
    int t = threadIdx.x, lane = t & 31, warp = t >> 5;

    float w[8];
#pragma unroll
    for (int m = 0; m < 8; m++)
        w[m] = nuP * __fdividef(1.f, g_T[cur][(lane * 8 + m) * 32]);

    float accf = 0.f;
    const int nWarps = 444 * 8;
    const int nBatch = BB / 2;   // batches of 2 rows
    int gw = blockIdx.x * 8 + warp;
    int colOff = lane * 8;

    for (int b = gw; b < nBatch; b += nWarps) {
        int row0 = b * 2;
#pragma unroll
        for (int r = 0; r < 2; r++) {
            int row = row0 + r;
            float q[8];
            {
                const float4* Cd = (const float4*)(coord + (size_t)row * KK + colOff);
                float4 c0 = Cd[0], c1 = Cd[1];
                q[0] = fabsf(c0.x); q[1] = fabsf(c0.y); q[2] = fabsf(c0.z); q[3] = fabsf(c0.w);
                q[4] = fabsf(c1.x); q[5] = fabsf(c1.y); q[6] = fabsf(c1.z); q[7] = fabsf(c1.w);
            }
            float mx = q[0];
#pragma unroll
            for (int m = 1; m < 8; m++) mx = fmaxf(mx, q[m]);
#pragma unroll
            for (int o = 16; o; o >>= 1) mx = fmaxf(mx, __shfl_xor_sync(0xffffffffu, mx, o));
            float e[8], z = 0.f;
#pragma unroll
            for (int m = 0; m < 8; m++) { e[m] = __expf(q[m] - mx); z += e[m]; }
#pragma unroll
            for (int o = 16; o; o >>= 1) z += __shfl_xor_sync(0xffffffffu, z, o);
            float rz = __fdividef(1.f, z);

            float a = g_a[row];
            float kk[8];
            ld256_el(g_K + (size_t)row * KK + colOff, kk);

            float contrib = 0.f;
#pragma unroll
            for (int m = 0; m < 8; m++) {
                float cm = -0.1f * __logf(kk[m] - 1e-8f);   // reconstruct C
                contrib += kk[m] * w[m] * cm * e[m];
            }
            accf += a * rz * contrib;
        }
    }

#pragma unroll
    for (int o = 16; o; o >>= 1) accf += __shfl_xor_sync(0xffffffffu, accf, o);
    __shared__ double sw[8];
    if (lane == 0) sw[warp] = (double)accf;
    __syncthreads();
    if (t == 0) {
        double s = 0.0;
#pragma unroll
        for (int i = 0; i < 8; i++) s += sw[i];
        atomicAdd(&g_sum, s);
    }
}

__global__ void k_write(float* out) { out[0] = (float)g_sum; }

// ---------------------------------------------------------------------------
extern "C" void kernel_launch(void* const* d_in, const int* in_sizes, int n_in,
                              void* d_out, int out_size) {
    const float* x     = (const float*)d_in[0];   // (65536, 128)
    const float* proto = (const float*)d_in[1];   // (256, 128)
    const float* coord = (const float*)d_in[2];   // (65536, 256)

    k_init<<<1, 256>>>(proto);
    k_xnorm<<<BB / 8, 256>>>(x);
    k_gemm<<<BB / 64, 256>>>(x);

    for (int it = 1; it <= 50; it++)
        k_iter<<<444, 256>>>((it - 1) % 3, it % 3, (it + 1) % 3);

    k_final<<<444, 256>>>(coord, 50 % 3);
    k_write<<<1, 1>>>((float*)d_out);
}

// round 6
// speedup vs baseline: 1.0021x; 1.0021x over previous
#include <cuda_runtime.h>
#include <cuda_bf16.h>
#include <math.h>

#define BB 65536
#define KK 256
#define DD 128

typedef unsigned long long u64;

// ---- scratch (static device globals; no allocation) ----
__device__ __nv_bfloat16 g_Kh[(size_t)BB * KK];  // K' in bf16 (32MB) — L2-resident
__device__ float g_ynT[DD * KK];         // normalized prototypes, k-major [k][j]
__device__ float g_xinv[BB];             // 1 / ||x_i||
__device__ float g_a[BB];                // exp(u)
__device__ float g_T[3][KK * 32];        // column sums, padded 128B apart
__device__ double g_sum;

// 256-bit L2-pinned load of 16 bf16 -> 16 floats
__device__ __forceinline__ void ld256_bf16_el(const __nv_bfloat16* p, float* f) {
    u64 q[4];
    asm volatile("ld.global.L2::evict_last.v4.b64 {%0,%1,%2,%3}, [%4];"
                 : "=l"(q[0]), "=l"(q[1]), "=l"(q[2]), "=l"(q[3]) : "l"(p));
#pragma unroll
    for (int i = 0; i < 4; i++) {
        unsigned lo = (unsigned)(q[i] & 0xffffffffull);
        unsigned hi = (unsigned)(q[i] >> 32);
        float2 f0 = __bfloat1622float2(*(__nv_bfloat162*)&lo);
        float2 f1 = __bfloat1622float2(*(__nv_bfloat162*)&hi);
        f[i * 4 + 0] = f0.x; f[i * 4 + 1] = f0.y;
        f[i * 4 + 2] = f1.x; f[i * 4 + 3] = f1.y;
    }
}

// ---------------------------------------------------------------------------
__global__ void k_init(const float* __restrict__ proto) {
    int j = threadIdx.x;  // 0..255
    float ss = 0.f;
#pragma unroll 8
    for (int k = 0; k < DD; k++) { float v = proto[j * DD + k]; ss += v * v; }
    float inv = __fdividef(1.f, fmaxf(sqrtf(ss), 1e-12f));
    for (int k = 0; k < DD; k++) g_ynT[k * KK + j] = proto[j * DD + k] * inv;
    const float nuP = 1.f / (float)KK + 1e-8f;
    g_T[0][j * 32] = nuP;   // makes w == 1 on iteration 1 (v0 = 0)
    g_T[1][j * 32] = 0.f;   // accumulation target of iteration 1
    if (j == 0) g_sum = 0.0;
}

// ---------------------------------------------------------------------------
__global__ void k_xnorm(const float* __restrict__ x) {
    int warp = threadIdx.x >> 5, lane = threadIdx.x & 31;
    int row = blockIdx.x * 8 + warp;
    float4 v = ((const float4*)(x + (size_t)row * DD))[lane];
    float ss = v.x * v.x + v.y * v.y + v.z * v.z + v.w * v.w;
#pragma unroll
    for (int o = 16; o; o >>= 1) ss += __shfl_xor_sync(0xffffffffu, ss, o);
    if (lane == 0) g_xinv[row] = __fdividef(1.f, fmaxf(sqrtf(ss), 1e-12f));
}

// ---------------------------------------------------------------------------
// cost GEMM: K' = exp(-10*(1 - xn.yn)) + 1e-8, stored bf16
// block = 256 threads, 64 rows x 256 cols per block, 8x8 register tile/thread
// ---------------------------------------------------------------------------
__global__ void k_gemm(const float* __restrict__ x) {
    __shared__ float ys[32 * 256];  // k-chunk of prototypes [kk][col]  (32KB)
    __shared__ float xs[64 * 32];   // x tile [row][kk]                 (8KB)
    __shared__ float xrn[64];

    int t = threadIdx.x;
    int rowBase = blockIdx.x * 64;
    if (t < 64) xrn[t] = g_xinv[rowBase + t];

    int tx = t & 31, ty = t >> 5;
    float acc[8][8];
#pragma unroll
    for (int i = 0; i < 8; i++)
#pragma unroll
        for (int j = 0; j < 8; j++) acc[i][j] = 0.f;

    for (int kc = 0; kc < 4; kc++) {
        __syncthreads();
        {
            const float4* src = (const float4*)(g_ynT + kc * 32 * 256);
            float4* dst = (float4*)ys;
#pragma unroll
            for (int i = 0; i < 8; i++) dst[t + i * 256] = src[t + i * 256];
        }
        {
#pragma unroll
            for (int i = 0; i < 2; i++) {
                int idx = t + i * 256;
                int r = idx >> 3;
                int c4 = idx & 7;
                float4 v = *(const float4*)(x + (size_t)(rowBase + r) * DD + kc * 32 + c4 * 4);
                *(float4*)&xs[r * 32 + c4 * 4] = v;
            }
        }
        __syncthreads();
#pragma unroll 4
        for (int k = 0; k < 32; k++) {
            float4 b0 = *(const float4*)&ys[k * 256 + tx * 8];
            float4 b1 = *(const float4*)&ys[k * 256 + tx * 8 + 4];
#pragma unroll
            for (int i = 0; i < 8; i++) {
                float a = xs[(ty * 8 + i) * 32 + k];
                acc[i][0] += a * b0.x; acc[i][1] += a * b0.y;
                acc[i][2] += a * b0.z; acc[i][3] += a * b0.w;
                acc[i][4] += a * b1.x; acc[i][5] += a * b1.y;
                acc[i][6] += a * b1.z; acc[i][7] += a * b1.w;
            }
        }
    }

#pragma unroll
    for (int i = 0; i < 8; i++) {
        int row = rowBase + ty * 8 + i;
        float inv = xrn[ty * 8 + i];
        float kv[8];
#pragma unroll
        for (int j = 0; j < 8; j++) {
            float c = 1.f - acc[i][j] * inv;
            kv[j] = __expf(-10.f * c) + 1e-8f;
        }
        __nv_bfloat162 h0 = __float22bfloat162_rn(make_float2(kv[0], kv[1]));
        __nv_bfloat162 h1 = __float22bfloat162_rn(make_float2(kv[2], kv[3]));
        __nv_bfloat162 h2 = __float22bfloat162_rn(make_float2(kv[4], kv[5]));
        __nv_bfloat162 h3 = __float22bfloat162_rn(make_float2(kv[6], kv[7]));
        uint4 s;
        s.x = *(unsigned*)&h0; s.y = *(unsigned*)&h1;
        s.z = *(unsigned*)&h2; s.w = *(unsigned*)&h3;
        *(uint4*)&g_Kh[(size_t)row * KK + tx * 8] = s;
    }
}

// ---------------------------------------------------------------------------
// Sinkhorn iteration helpers (bf16). Batch = 2 rows: lanes 0-15 cover row 2b
// (16 cols each), lanes 16-31 cover row 2b+1. One LDG.256 per lane per batch.
// ---------------------------------------------------------------------------
__device__ __forceinline__ void iter_loadh(int b, int half, int hl, float* f) {
    const __nv_bfloat16* p = g_Kh + ((size_t)b * 2 + half) * KK + hl * 16;
    ld256_bf16_el(p, f);
}

__device__ __forceinline__ void iter_compute(int b, int half, int hl,
                                             const float* f, const float* w,
                                             float* tj, float muP) {
    float s = 0.f;
#pragma unroll
    for (int m = 0; m < 16; m++) s += f[m] * w[m];
#pragma unroll
    for (int o = 8; o; o >>= 1) s += __shfl_xor_sync(0xffffffffu, s, o);
    float a = muP * __fdividef(1.f, s);
    if (hl == 0) g_a[b * 2 + half] = a;
#pragma unroll
    for (int m = 0; m < 16; m++) tj[m] += f[m] * a;
}

// ---------------------------------------------------------------------------
// fused Sinkhorn iteration: w = nu'/T_prev ; a_i = mu'/(K' w)_i ; T_cur += K'^T a
// persistent grid 444; double-buffered 2-row batches.
// ---------------------------------------------------------------------------
__global__ void __launch_bounds__(256, 3) k_iter(int prev, int cur, int clr) {
    const float nuP = 1.f / (float)KK + 1e-8f;
    const float muP = 1.f / (float)BB + 1e-8f;
    __shared__ float Ts2[16 * 256];   // [warp*2+half][col]

    int t = threadIdx.x, lane = t & 31, warp = t >> 5;
    int half = lane >> 4, hl = lane & 15;
    if (blockIdx.x == 0) g_T[clr][t * 32] = 0.f;  // clear buffer for NEXT kernel

    float w[16];
#pragma unroll
    for (int m = 0; m < 16; m++)
        w[m] = nuP * __fdividef(1.f, g_T[prev][(hl * 16 + m) * 32]);

    float tj[16];
#pragma unroll
    for (int m = 0; m < 16; m++) tj[m] = 0.f;

    const int nW = 444 * 8;          // 3552 warps
    const int nB = BB / 2;           // 32768 batches of 2 rows
    int gw = blockIdx.x * 8 + warp;

    float A[16], Bf[16];
    iter_loadh(gw, half, hl, A);     // gw < 3552 < nB always
    for (int b = gw; b < nB; b += 2 * nW) {
        int b1 = b + nW, b2 = b + 2 * nW;
        if (b1 < nB) iter_loadh(b1, half, hl, Bf);
        iter_compute(b, half, hl, A, w, tj, muP);
        if (b2 < nB) iter_loadh(b2, half, hl, A);
        if (b1 < nB) iter_compute(b1, half, hl, Bf, w, tj, muP);
    }

#pragma unroll
    for (int m = 0; m < 16; m++)
        Ts2[(warp * 2 + half) * 256 + hl * 16 + m] = tj[m];
    __syncthreads();
    {
        float s = 0.f;
#pragma unroll
        for (int r = 0; r < 16; r++) s += Ts2[r * 256 + t];
        atomicAdd(&g_T[cur][t * 32], s);
    }
}

// ---------------------------------------------------------------------------
// final: sum_ij a_i * K'_ij * w_j * C_ij * softmax(|coord_i|)_j
// C reconstructed: C = -0.1 * log(K' - 1e-8). Persistent grid 444.
// ---------------------------------------------------------------------------
__global__ void __launch_bounds__(256, 3) k_final(const float* __restrict__ coord, int cur) {
    const float nuP = 1.f / (float)KK + 1e-8f;
    int t = threadIdx.x, lane = t & 31, warp = t >> 5;

    float w[8];
#pragma unroll
    for (int m = 0; m < 8; m++)
        w[m] = nuP * __fdividef(1.f, g_T[cur][(lane * 8 + m) * 32]);

    float accf = 0.f;
    const int nWarps = 444 * 8;
    const int nBatch = BB / 2;   // batches of 2 rows
    int gw = blockIdx.x * 8 + warp;
    int colOff = lane * 8;

    for (int b = gw; b < nBatch; b += nWarps) {
        int row0 = b * 2;
#pragma unroll
        for (int r = 0; r < 2; r++) {
            int row = row0 + r;
            float q[8];
            {
                const float4* Cd = (const float4*)(coord + (size_t)row * KK + colOff);
                float4 c0 = Cd[0], c1 = Cd[1];
                q[0] = fabsf(c0.x); q[1] = fabsf(c0.y); q[2] = fabsf(c0.z); q[3] = fabsf(c0.w);
                q[4] = fabsf(c1.x); q[5] = fabsf(c1.y); q[6] = fabsf(c1.z); q[7] = fabsf(c1.w);
            }
            float mx = q[0];
#pragma unroll
            for (int m = 1; m < 8; m++) mx = fmaxf(mx, q[m]);
#pragma unroll
            for (int o = 16; o; o >>= 1) mx = fmaxf(mx, __shfl_xor_sync(0xffffffffu, mx, o));
            float e[8], z = 0.f;
#pragma unroll
            for (int m = 0; m < 8; m++) { e[m] = __expf(q[m] - mx); z += e[m]; }
#pragma unroll
            for (int o = 16; o; o >>= 1) z += __shfl_xor_sync(0xffffffffu, z, o);
            float rz = __fdividef(1.f, z);

            float a = g_a[row];
            float kk[8];
            {
                uint4 kv = *(const uint4*)&g_Kh[(size_t)row * KK + colOff];
                unsigned u[4] = {kv.x, kv.y, kv.z, kv.w};
#pragma unroll
                for (int i = 0; i < 4; i++) {
                    float2 f2 = __bfloat1622float2(*(__nv_bfloat162*)&u[i]);
                    kk[i * 2] = f2.x; kk[i * 2 + 1] = f2.y;
                }
            }

            float contrib = 0.f;
#pragma unroll
            for (int m = 0; m < 8; m++) {
                float cm = -0.1f * __logf(kk[m] - 1e-8f);   // reconstruct C
                contrib += kk[m] * w[m] * cm * e[m];
            }
            accf += a * rz * contrib;
        }
    }

#pragma unroll
    for (int o = 16; o; o >>= 1) accf += __shfl_xor_sync(0xffffffffu, accf, o);
    __shared__ double sw[8];
    if (lane == 0) sw[warp] = (double)accf;
    __syncthreads();
    if (t == 0) {
        double s = 0.0;
#pragma unroll
        for (int i = 0; i < 8; i++) s += sw[i];
        atomicAdd(&g_sum, s);
    }
}

__global__ void k_write(float* out) { out[0] = (float)g_sum; }

// ---------------------------------------------------------------------------
extern "C" void kernel_launch(void* const* d_in, const int* in_sizes, int n_in,
                              void* d_out, int out_size) {
    const float* x     = (const float*)d_in[0];   // (65536, 128)
    const float* proto = (const float*)d_in[1];   // (256, 128)
    const float* coord = (const float*)d_in[2];   // (65536, 256)

    k_init<<<1, 256>>>(proto);
    k_xnorm<<<BB / 8, 256>>>(x);
    k_gemm<<<BB / 64, 256>>>(x);

    for (int it = 1; it <= 50; it++)
        k_iter<<<444, 256>>>((it - 1) % 3, it % 3, (it + 1) % 3);

    k_final<<<444, 256>>>(coord, 50 % 3);
    k_write<<<1, 1>>>((float*)d_out);
}